// round 3
// baseline (speedup 1.0000x reference)
#include <cuda_runtime.h>
#include <cuda_bf16.h>
#include <cstdint>
#include <cstddef>

#define VOCAB 10000
#define EMBD  100
#define SEQ   80
#define BATCH 1024
#define UNITS 1024

// ---------------- static device scratch (no allocations allowed) ----------------
__device__ float          EP_g[(size_t)VOCAB * UNITS];            // emb@W0x + b0  (41 MB)
__device__ __nv_bfloat16  A0_g[2][(size_t)BATCH * 3 * UNITS];     // K1 A': [h0hi|h0hi|h0lo]
__device__ __nv_bfloat16  A1_g[2][(size_t)BATCH * 6 * UNITS];     // K2 A': [h0hi h1hi|h0hi h1hi|h0lo h1lo]
__device__ __nv_bfloat16  B0_g[(size_t)3 * UNITS * UNITS];        // [W0h_hi; W0h_lo; W0h_hi]
__device__ __nv_bfloat16  B1_g[(size_t)6 * UNITS * UNITS];        // [W1x_hi;W1h_hi; W1x_lo;W1h_lo; W1x_hi;W1h_hi]
__device__ float          H1f_g[(size_t)BATCH * UNITS];           // final-step h1 (fp32)

__device__ __forceinline__ uint32_t smem_u32(const void* p) {
    return (uint32_t)__cvta_generic_to_shared(p);
}

// ---------------- zero the state buffers read at t=0 ----------------
__global__ void zero_kernel() {
    const size_t n0 = (size_t)BATCH * 3 * UNITS;   // A0_g[1]
    const size_t n1 = (size_t)BATCH * 6 * UNITS;   // A1_g[0]
    const size_t tot = (n0 + n1) / 8;              // uint4 = 8 bf16
    uint4 z = make_uint4(0, 0, 0, 0);
    uint4* p0 = (uint4*)&A0_g[1][0];
    uint4* p1 = (uint4*)&A1_g[0][0];
    for (size_t i = (size_t)blockIdx.x * blockDim.x + threadIdx.x; i < tot;
         i += (size_t)gridDim.x * blockDim.x) {
        if (i < n0 / 8) p0[i] = z;
        else            p1[i - n0 / 8] = z;
    }
}

// ---------------- weight split prep ----------------
__global__ void prepB0(const float* __restrict__ W0h) {
    int i = blockIdx.x * blockDim.x + threadIdx.x;
    if (i >= 3 * UNITS * UNITS) return;
    int r = i / UNITS, c = i % UNITS;
    int block3 = r / UNITS;        // 0,1,2  -> [hi; lo; hi]
    int rr = r % UNITS;
    float w = W0h[(size_t)rr * UNITS + c];
    __nv_bfloat16 hi = __float2bfloat16(w);
    __nv_bfloat16 v = (block3 == 1) ? __float2bfloat16(w - __bfloat162float(hi)) : hi;
    B0_g[i] = v;
}

__global__ void prepB1(const float* __restrict__ W1x, const float* __restrict__ W1h) {
    int i = blockIdx.x * blockDim.x + threadIdx.x;
    if (i >= 6 * UNITS * UNITS) return;
    int r = i / UNITS, c = i % UNITS;
    int block3 = r / (2 * UNITS);  // 0,1,2  -> [hi; lo; hi]
    int rr = r % (2 * UNITS);
    float w = (rr < UNITS) ? W1x[(size_t)rr * UNITS + c]
                           : W1h[(size_t)(rr - UNITS) * UNITS + c];
    __nv_bfloat16 hi = __float2bfloat16(w);
    __nv_bfloat16 v = (block3 == 1) ? __float2bfloat16(w - __bfloat162float(hi)) : hi;
    B1_g[i] = v;
}

// ---------------- EP = emb @ W0x + b0  (fp32, M=10000, K=100, N=1024) ----------------
__global__ void __launch_bounds__(256) ep_kernel(const float* __restrict__ emb,
                                                 const float* __restrict__ W0x,
                                                 const float* __restrict__ b0) {
    __shared__ float se[32][EMBD];
    const int rowbase = blockIdx.y * 32;
    const int colbase = blockIdx.x * 128;
    for (int i = threadIdx.x; i < 32 * EMBD; i += 256) {
        int r = i / EMBD, c = i % EMBD;
        int gr = rowbase + r;
        se[r][c] = (gr < VOCAB) ? emb[(size_t)gr * EMBD + c] : 0.f;
    }
    __syncthreads();
    const int ct = threadIdx.x & 31;   // 32 col-groups of 4
    const int rt = threadIdx.x >> 5;   // 8 row-groups of 4
    const int col = colbase + ct * 4;
    float acc[4][4] = {};
    for (int k = 0; k < EMBD; k++) {
        float4 wv = *(const float4*)&W0x[(size_t)k * UNITS + col];
        #pragma unroll
        for (int i = 0; i < 4; i++) {
            float av = se[rt * 4 + i][k];
            acc[i][0] += av * wv.x; acc[i][1] += av * wv.y;
            acc[i][2] += av * wv.z; acc[i][3] += av * wv.w;
        }
    }
    float4 bv = *(const float4*)&b0[col];
    #pragma unroll
    for (int i = 0; i < 4; i++) {
        int gr = rowbase + rt * 4 + i;
        if (gr < VOCAB) {
            float4 o = make_float4(acc[i][0] + bv.x, acc[i][1] + bv.y,
                                   acc[i][2] + bv.z, acc[i][3] + bv.w);
            *(float4*)&EP_g[(size_t)gr * UNITS + col] = o;
        }
    }
}

// ---------------- main recurrent GEMM (bf16x3 via warp MMA) ----------------
// EPI=0: h0_t = tanh(EP[x[b,t]] + h0_{t-1} @ W0h)        A=A0_g[(t+1)&1], K=3072
// EPI=1: h1_t = tanh([h0_t|h1_{t-1}] @ [W1x;W1h] + b1)   A=A1_g[t&1],     K=6144
#define BM 128
#define BN 64
#define BK 32

template <int EPI>
__global__ void __launch_bounds__(256) rnn_gemm(int t, const int* __restrict__ xids,
                                                const float* __restrict__ b1vec) {
    constexpr int K  = EPI ? (6 * UNITS) : (3 * UNITS);
    constexpr int KT = K / BK;

    const __nv_bfloat16* __restrict__ Ag = EPI ? &A1_g[t & 1][0] : &A0_g[(t + 1) & 1][0];
    const __nv_bfloat16* __restrict__ Bg = EPI ? B1_g : B0_g;

    __shared__ __align__(16) __nv_bfloat16 As[3][BM][BK + 8];  // +16B pad: conflict-free ldmatrix
    __shared__ __align__(16) __nv_bfloat16 Bs[3][BK][BN + 8];

    const int tid  = threadIdx.x;
    const int lane = tid & 31;
    const int wid  = tid >> 5;
    const int wm   = wid >> 1;      // 4 warp rows (32 each)
    const int wn   = wid & 1;       // 2 warp cols (32 each)
    const int bm   = blockIdx.y * BM;
    const int bn   = blockIdx.x * BN;

    auto issue = [&](int kb, int s) {
        #pragma unroll
        for (int j = 0; j < 2; j++) {
            int idx = tid * 2 + j;          // 0..511
            int r = idx >> 2, c = idx & 3;  // 128 rows x 4 chunks of 8 bf16
            const __nv_bfloat16* src = Ag + (size_t)(bm + r) * K + kb * BK + c * 8;
            uint32_t dst = smem_u32(&As[s][r][c * 8]);
            asm volatile("cp.async.cg.shared.global [%0], [%1], 16;\n" ::"r"(dst), "l"(src));
        }
        {
            int r = tid >> 3, c = tid & 7;  // 32 rows x 8 chunks of 8 bf16
            const __nv_bfloat16* src = Bg + (size_t)(kb * BK + r) * UNITS + bn + c * 8;
            uint32_t dst = smem_u32(&Bs[s][r][c * 8]);
            asm volatile("cp.async.cg.shared.global [%0], [%1], 16;\n" ::"r"(dst), "l"(src));
        }
        asm volatile("cp.async.commit_group;\n");
    };

    issue(0, 0);
    issue(1, 1);

    float acc[2][4][4];
    #pragma unroll
    for (int i = 0; i < 2; i++)
        #pragma unroll
        for (int j = 0; j < 4; j++)
            #pragma unroll
            for (int q = 0; q < 4; q++) acc[i][j][q] = 0.f;

    for (int kb = 0; kb < KT; kb++) {
        if (kb == KT - 1) asm volatile("cp.async.wait_group 0;\n");
        else              asm volatile("cp.async.wait_group 1;\n");
        __syncthreads();
        const int s = kb % 3;

        #pragma unroll
        for (int ks = 0; ks < 2; ks++) {
            uint32_t a[2][4], b[2][4];
            #pragma unroll
            for (int mi = 0; mi < 2; mi++) {
                uint32_t addr = smem_u32(&As[s][wm * 32 + mi * 16 + (lane & 15)]
                                           [ks * 16 + ((lane >> 4) << 3)]);
                asm volatile("ldmatrix.sync.aligned.m8n8.x4.shared.b16 {%0,%1,%2,%3}, [%4];\n"
                             : "=r"(a[mi][0]), "=r"(a[mi][1]), "=r"(a[mi][2]), "=r"(a[mi][3])
                             : "r"(addr));
            }
            #pragma unroll
            for (int nh = 0; nh < 2; nh++) {
                uint32_t addr = smem_u32(&Bs[s][ks * 16 + (lane & 15)]
                                           [wn * 32 + nh * 16 + ((lane >> 4) << 3)]);
                asm volatile("ldmatrix.sync.aligned.m8n8.x4.trans.shared.b16 {%0,%1,%2,%3}, [%4];\n"
                             : "=r"(b[nh][0]), "=r"(b[nh][1]), "=r"(b[nh][2]), "=r"(b[nh][3])
                             : "r"(addr));
            }
            #pragma unroll
            for (int mi = 0; mi < 2; mi++)
                #pragma unroll
                for (int nn = 0; nn < 4; nn++) {
                    uint32_t bb0 = b[nn >> 1][(nn & 1) * 2];
                    uint32_t bb1 = b[nn >> 1][(nn & 1) * 2 + 1];
                    float* c = acc[mi][nn];
                    asm volatile(
                        "mma.sync.aligned.m16n8k16.row.col.f32.bf16.bf16.f32 "
                        "{%0,%1,%2,%3}, {%4,%5,%6,%7}, {%8,%9}, {%0,%1,%2,%3};\n"
                        : "+f"(c[0]), "+f"(c[1]), "+f"(c[2]), "+f"(c[3])
                        : "r"(a[mi][0]), "r"(a[mi][1]), "r"(a[mi][2]), "r"(a[mi][3]),
                          "r"(bb0), "r"(bb1));
                }
        }
        if (kb + 2 < KT) issue(kb + 2, (kb + 2) % 3);
    }

    // ------------- epilogue: tanh + hi/lo split writes -------------
    const int r0 = lane >> 2;        // 0..7
    const int cp = lane & 3;         // col pair index
    #pragma unroll
    for (int mi = 0; mi < 2; mi++) {
        #pragma unroll
        for (int rr = 0; rr < 2; rr++) {
            const int b = bm + wm * 32 + mi * 16 + r0 + rr * 8;   // batch row
            int xi = 0;
            if (EPI == 0) xi = xids[b * SEQ + t];
            const float* ep = (EPI == 0) ? &EP_g[(size_t)xi * UNITS] : nullptr;
            #pragma unroll
            for (int nn = 0; nn < 4; nn++) {
                const int u = bn + wn * 32 + nn * 8 + cp * 2;     // unit col
                float add0, add1;
                if (EPI == 0) { add0 = ep[u];      add1 = ep[u + 1]; }
                else          { add0 = b1vec[u];   add1 = b1vec[u + 1]; }
                float h0v = tanhf(acc[mi][nn][rr * 2 + 0] + add0);
                float h1v = tanhf(acc[mi][nn][rr * 2 + 1] + add1);
                __nv_bfloat16 hiA = __float2bfloat16(h0v);
                __nv_bfloat16 hiB = __float2bfloat16(h1v);
                __nv_bfloat16 loA = __float2bfloat16(h0v - __bfloat162float(hiA));
                __nv_bfloat16 loB = __float2bfloat16(h1v - __bfloat162float(hiB));
                __nv_bfloat162 hi2; hi2.x = hiA; hi2.y = hiB;
                __nv_bfloat162 lo2; lo2.x = loA; lo2.y = loB;
                if (EPI == 0) {
                    const int pn = t & 1;
                    size_t r3 = (size_t)b * (3 * UNITS);
                    size_t r6 = (size_t)b * (6 * UNITS);
                    *(__nv_bfloat162*)&A0_g[pn][r3 + u]             = hi2;
                    *(__nv_bfloat162*)&A0_g[pn][r3 + UNITS + u]     = hi2;
                    *(__nv_bfloat162*)&A0_g[pn][r3 + 2 * UNITS + u] = lo2;
                    *(__nv_bfloat162*)&A1_g[pn][r6 + u]             = hi2;
                    *(__nv_bfloat162*)&A1_g[pn][r6 + 2 * UNITS + u] = hi2;
                    *(__nv_bfloat162*)&A1_g[pn][r6 + 4 * UNITS + u] = lo2;
                } else {
                    const int pn = (t + 1) & 1;
                    size_t r6 = (size_t)b * (6 * UNITS);
                    *(__nv_bfloat162*)&A1_g[pn][r6 + UNITS + u]     = hi2;
                    *(__nv_bfloat162*)&A1_g[pn][r6 + 3 * UNITS + u] = hi2;
                    *(__nv_bfloat162*)&A1_g[pn][r6 + 5 * UNITS + u] = lo2;
                    if (t == SEQ - 1) {
                        H1f_g[(size_t)b * UNITS + u]     = h0v;
                        H1f_g[(size_t)b * UNITS + u + 1] = h1v;
                    }
                }
            }
        }
    }
}

// ---------------- output: sigmoid(h1 @ Wout + bout) ----------------
__global__ void out_kernel(const float* __restrict__ Wout, const float* __restrict__ bout,
                           float* __restrict__ out) {
    const int b = blockIdx.x;
    float s = 0.f;
    for (int u = threadIdx.x; u < UNITS; u += blockDim.x)
        s += H1f_g[(size_t)b * UNITS + u] * Wout[u];
    #pragma unroll
    for (int o = 16; o; o >>= 1) s += __shfl_xor_sync(0xffffffff, s, o);
    __shared__ float red[4];
    if ((threadIdx.x & 31) == 0) red[threadIdx.x >> 5] = s;
    __syncthreads();
    if (threadIdx.x == 0) {
        float tot = red[0] + red[1] + red[2] + red[3] + bout[0];
        out[b] = 1.f / (1.f + expf(-tot));
    }
}

// ---------------- launcher ----------------
extern "C" void kernel_launch(void* const* d_in, const int* in_sizes, int n_in,
                              void* d_out, int out_size) {
    (void)in_sizes; (void)n_in; (void)out_size;
    const int*   x    = (const int*)d_in[0];
    const float* emb  = (const float*)d_in[1];
    const float* W0x  = (const float*)d_in[2];
    const float* W0h  = (const float*)d_in[3];
    const float* b0   = (const float*)d_in[4];
    const float* W1x  = (const float*)d_in[5];
    const float* W1h  = (const float*)d_in[6];
    const float* b1   = (const float*)d_in[7];
    const float* Wout = (const float*)d_in[8];
    const float* bout = (const float*)d_in[9];
    float* out = (float*)d_out;

    zero_kernel<<<4608, 256>>>();
    prepB0<<<(3 * UNITS * UNITS + 255) / 256, 256>>>(W0h);
    prepB1<<<(6 * UNITS * UNITS + 255) / 256, 256>>>(W1x, W1h);
    ep_kernel<<<dim3(UNITS / 128, (VOCAB + 31) / 32), 256>>>(emb, W0x, b0);

    for (int t = 0; t < SEQ; t++) {
        rnn_gemm<0><<<dim3(UNITS / BN, BATCH / BM), 256>>>(t, x, b1);
        rnn_gemm<1><<<dim3(UNITS / BN, BATCH / BM), 256>>>(t, x, b1);
    }
    out_kernel<<<BATCH, 128>>>(Wout, bout, out);
}

// round 4
// speedup vs baseline: 1.9831x; 1.9831x over previous
#include <cuda_runtime.h>
#include <cuda_fp16.h>
#include <cstdint>
#include <cstddef>

#define VOCAB 10000
#define EMBD  100
#define SEQ   80
#define BATCH 1024
#define UNITS 1024

// ---------------- static device scratch (no allocations allowed) ----------------
__device__ float   EP_g[(size_t)VOCAB * UNITS];             // emb@W0x + b0  (41 MB)
__device__ __half  A0_g[2][(size_t)BATCH * UNITS];          // h0 (fp16), ping-pong
__device__ __half  A1_g[2][(size_t)BATCH * 2 * UNITS];      // [h0 | h1] (fp16), ping-pong
__device__ __half  B0_g[(size_t)2 * UNITS * UNITS];         // [W0h_hi ; W0h_lo]   (k-major)
__device__ __half  B1_g[(size_t)4 * UNITS * UNITS];         // [W1x_hi;W1h_hi ; W1x_lo;W1h_lo]
__device__ float   H1f_g[(size_t)BATCH * UNITS];            // final-step h1 (fp32)

__device__ __forceinline__ uint32_t smem_u32(const void* p) {
    return (uint32_t)__cvta_generic_to_shared(p);
}

// ---------------- zero the state buffers read at t=0 ----------------
__global__ void zero_kernel() {
    const size_t n0 = (size_t)BATCH * UNITS;        // A0_g[1]
    const size_t n1 = (size_t)BATCH * 2 * UNITS;    // A1_g[0]
    const size_t tot = (n0 + n1) / 8;               // uint4 = 8 halfs
    uint4 z = make_uint4(0, 0, 0, 0);
    uint4* p0 = (uint4*)&A0_g[1][0];
    uint4* p1 = (uint4*)&A1_g[0][0];
    for (size_t i = (size_t)blockIdx.x * blockDim.x + threadIdx.x; i < tot;
         i += (size_t)gridDim.x * blockDim.x) {
        if (i < n0 / 8) p0[i] = z;
        else            p1[i - n0 / 8] = z;
    }
}

// ---------------- weight split prep (fp16 hi/lo) ----------------
__global__ void prepB0(const float* __restrict__ W0h) {
    int i = blockIdx.x * blockDim.x + threadIdx.x;
    if (i >= 2 * UNITS * UNITS) return;
    int r = i / UNITS, c = i % UNITS;
    int lo = r / UNITS;            // 0 = hi block, 1 = lo block
    int rr = r % UNITS;
    float w = W0h[(size_t)rr * UNITS + c];
    __half hi = __float2half_rn(w);
    B0_g[i] = lo ? __float2half_rn(w - __half2float(hi)) : hi;
}

__global__ void prepB1(const float* __restrict__ W1x, const float* __restrict__ W1h) {
    int i = blockIdx.x * blockDim.x + threadIdx.x;
    if (i >= 4 * UNITS * UNITS) return;
    int r = i / UNITS, c = i % UNITS;
    int lo = r / (2 * UNITS);      // 0 = hi block, 1 = lo block
    int rr = r % (2 * UNITS);
    float w = (rr < UNITS) ? W1x[(size_t)rr * UNITS + c]
                           : W1h[(size_t)(rr - UNITS) * UNITS + c];
    __half hi = __float2half_rn(w);
    B1_g[i] = lo ? __float2half_rn(w - __half2float(hi)) : hi;
}

// ---------------- EP = emb @ W0x + b0  (fp32, M=10000, K=100, N=1024) ----------------
__global__ void __launch_bounds__(256) ep_kernel(const float* __restrict__ emb,
                                                 const float* __restrict__ W0x,
                                                 const float* __restrict__ b0) {
    __shared__ float se[32][EMBD];
    const int rowbase = blockIdx.y * 32;
    const int colbase = blockIdx.x * 128;
    for (int i = threadIdx.x; i < 32 * EMBD; i += 256) {
        int r = i / EMBD, c = i % EMBD;
        int gr = rowbase + r;
        se[r][c] = (gr < VOCAB) ? emb[(size_t)gr * EMBD + c] : 0.f;
    }
    __syncthreads();
    const int ct = threadIdx.x & 31;
    const int rt = threadIdx.x >> 5;
    const int col = colbase + ct * 4;
    float acc[4][4] = {};
    for (int k = 0; k < EMBD; k++) {
        float4 wv = *(const float4*)&W0x[(size_t)k * UNITS + col];
        #pragma unroll
        for (int i = 0; i < 4; i++) {
            float av = se[rt * 4 + i][k];
            acc[i][0] += av * wv.x; acc[i][1] += av * wv.y;
            acc[i][2] += av * wv.z; acc[i][3] += av * wv.w;
        }
    }
    float4 bv = *(const float4*)&b0[col];
    #pragma unroll
    for (int i = 0; i < 4; i++) {
        int gr = rowbase + rt * 4 + i;
        if (gr < VOCAB) {
            float4 o = make_float4(acc[i][0] + bv.x, acc[i][1] + bv.y,
                                   acc[i][2] + bv.z, acc[i][3] + bv.w);
            *(float4*)&EP_g[(size_t)gr * UNITS + col] = o;
        }
    }
}

// ---------------- main recurrent GEMM (fp16, 2-term B split) ----------------
// EPI=0: h0_t = tanh(EP[x[b,t]] + h0_{t-1} @ (W0h_hi+W0h_lo))      KU=1024
// EPI=1: h1_t = tanh([h0_t|h1_{t-1}] @ ([W1x;W1h]_hi+lo) + b1)     KU=2048
#define BM 128
#define BN 64
#define BK 32

#define AS_PITCH 40                    // 32 + 8 pad (80 B rows, conflict-free)
#define BS_PITCH 72                    // 64 + 8 pad (144 B rows, conflict-free)
#define AS_STAGE (BM * AS_PITCH)       // 5120 halfs
#define BS_STAGE (2 * BK * BS_PITCH)   // 4608 halfs (hi + lo)
#define SMEM_HALFS (3 * (AS_STAGE + BS_STAGE))
#define SMEM_BYTES (SMEM_HALFS * 2)    // 58368 B

template <int EPI>
__global__ void __launch_bounds__(256) rnn_gemm(int t, const int* __restrict__ xids,
                                                const float* __restrict__ b1vec) {
    constexpr int KU = EPI ? (2 * UNITS) : UNITS;   // unique K
    constexpr int KT = KU / BK;

    const __half* __restrict__ Ag = EPI ? &A1_g[t & 1][0] : &A0_g[(t + 1) & 1][0];
    const __half* __restrict__ Bg = EPI ? B1_g : B0_g;

    extern __shared__ __align__(16) __half sm[];
    // As(s,r,c)      = sm[s*AS_STAGE + r*AS_PITCH + c]
    // Bs(s,buf,r,c)  = sm[3*AS_STAGE + s*BS_STAGE + buf*BK*BS_PITCH + r*BS_PITCH + c]
    __half* AsBase = sm;
    __half* BsBase = sm + 3 * AS_STAGE;

    const int tid  = threadIdx.x;
    const int lane = tid & 31;
    const int wid  = tid >> 5;
    const int wm   = wid >> 1;      // 4 warp rows (32 rows each)
    const int wn   = wid & 1;       // 2 warp cols (32 cols each)
    const int bm   = blockIdx.y * BM;
    const int bn   = blockIdx.x * BN;

    auto issue = [&](int kb, int s) {
        // A tile: 128x32 halfs = 8 KB = 512 x 16B; 2 per thread
        #pragma unroll
        for (int j = 0; j < 2; j++) {
            int idx = tid * 2 + j;
            int r = idx >> 2, c = idx & 3;
            const __half* src = Ag + (size_t)(bm + r) * KU + kb * BK + c * 8;
            uint32_t dst = smem_u32(AsBase + s * AS_STAGE + r * AS_PITCH + c * 8);
            asm volatile("cp.async.cg.shared.global [%0], [%1], 16;\n" ::"r"(dst), "l"(src));
        }
        // Bhi + Blo tiles: each 32x64 = 4 KB = 256 x 16B; 1 each per thread
        {
            int r = tid >> 3, c = tid & 7;
            const __half* srcH = Bg + (size_t)(kb * BK + r) * UNITS + bn + c * 8;
            const __half* srcL = srcH + (size_t)KU * UNITS;
            uint32_t dstH = smem_u32(BsBase + s * BS_STAGE + r * BS_PITCH + c * 8);
            uint32_t dstL = dstH + BK * BS_PITCH * 2;
            asm volatile("cp.async.cg.shared.global [%0], [%1], 16;\n" ::"r"(dstH), "l"(srcH));
            asm volatile("cp.async.cg.shared.global [%0], [%1], 16;\n" ::"r"(dstL), "l"(srcL));
        }
        asm volatile("cp.async.commit_group;\n");
    };

    issue(0, 0);
    issue(1, 1);

    float acc[2][4][4];
    #pragma unroll
    for (int i = 0; i < 2; i++)
        #pragma unroll
        for (int j = 0; j < 4; j++)
            #pragma unroll
            for (int q = 0; q < 4; q++) acc[i][j][q] = 0.f;

    for (int kb = 0; kb < KT; kb++) {
        if (kb == KT - 1) asm volatile("cp.async.wait_group 0;\n");
        else              asm volatile("cp.async.wait_group 1;\n");
        __syncthreads();
        if (kb + 2 < KT) issue(kb + 2, (kb + 2) % 3);   // prefetch early
        const int s = kb % 3;

        #pragma unroll
        for (int ks = 0; ks < 2; ks++) {
            uint32_t a[2][4], bh[2][4], bl[2][4];
            #pragma unroll
            for (int mi = 0; mi < 2; mi++) {
                uint32_t addr = smem_u32(AsBase + s * AS_STAGE
                                         + (wm * 32 + mi * 16 + (lane & 15)) * AS_PITCH
                                         + ks * 16 + ((lane >> 4) << 3));
                asm volatile("ldmatrix.sync.aligned.m8n8.x4.shared.b16 {%0,%1,%2,%3}, [%4];\n"
                             : "=r"(a[mi][0]), "=r"(a[mi][1]), "=r"(a[mi][2]), "=r"(a[mi][3])
                             : "r"(addr));
            }
            #pragma unroll
            for (int nh = 0; nh < 2; nh++) {
                uint32_t addrH = smem_u32(BsBase + s * BS_STAGE
                                          + (ks * 16 + (lane & 15)) * BS_PITCH
                                          + wn * 32 + nh * 16 + ((lane >> 4) << 3));
                asm volatile("ldmatrix.sync.aligned.m8n8.x4.trans.shared.b16 {%0,%1,%2,%3}, [%4];\n"
                             : "=r"(bh[nh][0]), "=r"(bh[nh][1]), "=r"(bh[nh][2]), "=r"(bh[nh][3])
                             : "r"(addrH));
                uint32_t addrL = addrH + BK * BS_PITCH * 2;
                asm volatile("ldmatrix.sync.aligned.m8n8.x4.trans.shared.b16 {%0,%1,%2,%3}, [%4];\n"
                             : "=r"(bl[nh][0]), "=r"(bl[nh][1]), "=r"(bl[nh][2]), "=r"(bl[nh][3])
                             : "r"(addrL));
            }
            // two passes (hi, lo) reusing the same A fragments
            #pragma unroll
            for (int p = 0; p < 2; p++) {
                #pragma unroll
                for (int mi = 0; mi < 2; mi++)
                    #pragma unroll
                    for (int nn = 0; nn < 4; nn++) {
                        uint32_t b0r = p ? bl[nn >> 1][(nn & 1) * 2]     : bh[nn >> 1][(nn & 1) * 2];
                        uint32_t b1r = p ? bl[nn >> 1][(nn & 1) * 2 + 1] : bh[nn >> 1][(nn & 1) * 2 + 1];
                        float* c = acc[mi][nn];
                        asm volatile(
                            "mma.sync.aligned.m16n8k16.row.col.f32.f16.f16.f32 "
                            "{%0,%1,%2,%3}, {%4,%5,%6,%7}, {%8,%9}, {%0,%1,%2,%3};\n"
                            : "+f"(c[0]), "+f"(c[1]), "+f"(c[2]), "+f"(c[3])
                            : "r"(a[mi][0]), "r"(a[mi][1]), "r"(a[mi][2]), "r"(a[mi][3]),
                              "r"(b0r), "r"(b1r));
                    }
            }
        }
    }

    // ------------- epilogue: tanh + fp16 state writes -------------
    const int r0 = lane >> 2;
    const int cp = lane & 3;
    #pragma unroll
    for (int mi = 0; mi < 2; mi++) {
        #pragma unroll
        for (int rr = 0; rr < 2; rr++) {
            const int b = bm + wm * 32 + mi * 16 + r0 + rr * 8;   // batch row
            int xi = 0;
            if (EPI == 0) xi = xids[b * SEQ + t];
            const float* ep = (EPI == 0) ? &EP_g[(size_t)xi * UNITS] : nullptr;
            #pragma unroll
            for (int nn = 0; nn < 4; nn++) {
                const int u = bn + wn * 32 + nn * 8 + cp * 2;     // unit col
                float add0, add1;
                if (EPI == 0) { add0 = ep[u];    add1 = ep[u + 1]; }
                else          { add0 = b1vec[u]; add1 = b1vec[u + 1]; }
                float v0 = tanhf(acc[mi][nn][rr * 2 + 0] + add0);
                float v1 = tanhf(acc[mi][nn][rr * 2 + 1] + add1);
                __half2 h2 = __halves2half2(__float2half_rn(v0), __float2half_rn(v1));
                if (EPI == 0) {
                    const int pn = t & 1;
                    *(__half2*)&A0_g[pn][(size_t)b * UNITS + u]           = h2;
                    *(__half2*)&A1_g[pn][(size_t)b * (2 * UNITS) + u]     = h2;
                } else {
                    const int pn = (t + 1) & 1;
                    *(__half2*)&A1_g[pn][(size_t)b * (2 * UNITS) + UNITS + u] = h2;
                    if (t == SEQ - 1) {
                        H1f_g[(size_t)b * UNITS + u]     = v0;
                        H1f_g[(size_t)b * UNITS + u + 1] = v1;
                    }
                }
            }
        }
    }
}

// ---------------- output: sigmoid(h1 @ Wout + bout) ----------------
__global__ void out_kernel(const float* __restrict__ Wout, const float* __restrict__ bout,
                           float* __restrict__ out) {
    const int b = blockIdx.x;
    float s = 0.f;
    for (int u = threadIdx.x; u < UNITS; u += blockDim.x)
        s += H1f_g[(size_t)b * UNITS + u] * Wout[u];
    #pragma unroll
    for (int o = 16; o; o >>= 1) s += __shfl_xor_sync(0xffffffff, s, o);
    __shared__ float red[4];
    if ((threadIdx.x & 31) == 0) red[threadIdx.x >> 5] = s;
    __syncthreads();
    if (threadIdx.x == 0) {
        float tot = red[0] + red[1] + red[2] + red[3] + bout[0];
        out[b] = 1.f / (1.f + expf(-tot));
    }
}

// ---------------- launcher ----------------
extern "C" void kernel_launch(void* const* d_in, const int* in_sizes, int n_in,
                              void* d_out, int out_size) {
    (void)in_sizes; (void)n_in; (void)out_size;
    const int*   x    = (const int*)d_in[0];
    const float* emb  = (const float*)d_in[1];
    const float* W0x  = (const float*)d_in[2];
    const float* W0h  = (const float*)d_in[3];
    const float* b0   = (const float*)d_in[4];
    const float* W1x  = (const float*)d_in[5];
    const float* W1h  = (const float*)d_in[6];
    const float* b1   = (const float*)d_in[7];
    const float* Wout = (const float*)d_in[8];
    const float* bout = (const float*)d_in[9];
    float* out = (float*)d_out;

    cudaFuncSetAttribute(rnn_gemm<0>, cudaFuncAttributeMaxDynamicSharedMemorySize, SMEM_BYTES);
    cudaFuncSetAttribute(rnn_gemm<1>, cudaFuncAttributeMaxDynamicSharedMemorySize, SMEM_BYTES);

    zero_kernel<<<1536, 256>>>();
    prepB0<<<(2 * UNITS * UNITS + 255) / 256, 256>>>(W0h);
    prepB1<<<(4 * UNITS * UNITS + 255) / 256, 256>>>(W1x, W1h);
    ep_kernel<<<dim3(UNITS / 128, (VOCAB + 31) / 32), 256>>>(emb, W0x, b0);

    for (int t = 0; t < SEQ; t++) {
        rnn_gemm<0><<<dim3(UNITS / BN, BATCH / BM), 256, SMEM_BYTES>>>(t, x, b1);
        rnn_gemm<1><<<dim3(UNITS / BN, BATCH / BM), 256, SMEM_BYTES>>>(t, x, b1);
    }
    out_kernel<<<BATCH, 128>>>(Wout, bout, out);
}

// round 6
// speedup vs baseline: 2.1475x; 1.0829x over previous
#include <cuda_runtime.h>
#include <cuda_fp16.h>
#include <cstdint>
#include <cstddef>

#define VOCAB 10000
#define EMBD  100
#define SEQ   80
#define BATCH 1024
#define UNITS 1024

// ---------------- static device scratch (no allocations allowed) ----------------
__device__ float   EP_g[(size_t)VOCAB * UNITS];             // emb@W0x + b0
__device__ __half  A0_g[2][(size_t)BATCH * UNITS];          // h0 fp16 ping-pong
__device__ __half  A1_g[2][(size_t)BATCH * 2 * UNITS];      // [h0|h1] fp16 ping-pong
__device__ __half  B0_g[(size_t)2 * UNITS * UNITS];         // [W0h_hi ; W0h_lo]  k-major
__device__ __half  B1_g[(size_t)4 * UNITS * UNITS];         // [W1x;W1h]_hi ; _lo k-major

__device__ __forceinline__ uint32_t smem_u32(const void* p) {
    return (uint32_t)__cvta_generic_to_shared(p);
}

// ---------------- fused prep: zero state + split both weight matrices ----------------
__global__ void prep_all(const float* __restrict__ W0h,
                         const float* __restrict__ W1x, const float* __restrict__ W1h) {
    const int nthr = gridDim.x * blockDim.x;
    const int tid  = blockIdx.x * blockDim.x + threadIdx.x;

    // zero A0_g[1] (1M halfs) + A1_g[0] (2M halfs), uint4 strides
    {
        const size_t n0 = (size_t)BATCH * UNITS / 8;
        const size_t n1 = (size_t)BATCH * 2 * UNITS / 8;
        uint4 z = make_uint4(0, 0, 0, 0);
        uint4* p0 = (uint4*)&A0_g[1][0];
        uint4* p1 = (uint4*)&A1_g[0][0];
        for (size_t i = tid; i < n0 + n1; i += nthr) {
            if (i < n0) p0[i] = z;
            else        p1[i - n0] = z;
        }
    }
    // B0 split: [hi(1024 rows) ; lo(1024 rows)] x 1024 cols
    for (int i = tid; i < 2 * UNITS * UNITS; i += nthr) {
        int r = i / UNITS, c = i % UNITS;
        int lo = r / UNITS;
        int rr = r % UNITS;
        float w = W0h[(size_t)rr * UNITS + c];
        __half hi = __float2half_rn(w);
        B0_g[i] = lo ? __float2half_rn(w - __half2float(hi)) : hi;
    }
    // B1 split: [ [W1x;W1h]_hi (2048 rows) ; _lo (2048 rows) ] x 1024 cols
    for (int i = tid; i < 4 * UNITS * UNITS; i += nthr) {
        int r = i / UNITS, c = i % UNITS;
        int lo = r / (2 * UNITS);
        int rr = r % (2 * UNITS);
        float w = (rr < UNITS) ? W1x[(size_t)rr * UNITS + c]
                               : W1h[(size_t)(rr - UNITS) * UNITS + c];
        __half hi = __float2half_rn(w);
        B1_g[i] = lo ? __float2half_rn(w - __half2float(hi)) : hi;
    }
}

// ---------------- EP = emb @ W0x + b0  (fp32, M=10000, K=100, N=1024) ----------------
__global__ void __launch_bounds__(256) ep_kernel(const float* __restrict__ emb,
                                                 const float* __restrict__ W0x,
                                                 const float* __restrict__ b0) {
    __shared__ float se[32][EMBD];
    const int rowbase = blockIdx.y * 32;
    const int colbase = blockIdx.x * 128;
    for (int i = threadIdx.x; i < 32 * EMBD; i += 256) {
        int r = i / EMBD, c = i % EMBD;
        int gr = rowbase + r;
        se[r][c] = (gr < VOCAB) ? emb[(size_t)gr * EMBD + c] : 0.f;
    }
    __syncthreads();
    const int ct = threadIdx.x & 31;
    const int rt = threadIdx.x >> 5;
    const int col = colbase + ct * 4;
    float acc[4][4] = {};
    for (int k = 0; k < EMBD; k++) {
        float4 wv = *(const float4*)&W0x[(size_t)k * UNITS + col];
        #pragma unroll
        for (int i = 0; i < 4; i++) {
            float av = se[rt * 4 + i][k];
            acc[i][0] += av * wv.x; acc[i][1] += av * wv.y;
            acc[i][2] += av * wv.z; acc[i][3] += av * wv.w;
        }
    }
    float4 bv = *(const float4*)&b0[col];
    #pragma unroll
    for (int i = 0; i < 4; i++) {
        int gr = rowbase + rt * 4 + i;
        if (gr < VOCAB) {
            float4 o = make_float4(acc[i][0] + bv.x, acc[i][1] + bv.y,
                                   acc[i][2] + bv.z, acc[i][3] + bv.w);
            *(float4*)&EP_g[(size_t)gr * UNITS + col] = o;
        }
    }
}

// ---------------- main recurrent GEMM (fp16, 2-term B split) ----------------
// EPI=0: h0_t = tanh(EP[x[b,t]] + h0_{t-1} @ (W0h_hi+W0h_lo))      KU=1024
// EPI=1: h1_t = tanh([h0_t|h1_{t-1}] @ (W_hi+W_lo) + b1)           KU=2048
// CTA: 128 threads = 4 warps (2x2), tile BM=64 x BN=64, BK=64, 3-stage cp.async.
#define BM 64
#define BN 64
#define BK 64

#define APITCH 72                        // 64 + 8 halfs pad (144 B rows)
#define AS_STAGE (BM * APITCH)           // 4608 halfs
#define BS_STAGE (2 * BK * APITCH)       // 9216 halfs (hi + lo)
#define STAGE_HALFS (AS_STAGE + BS_STAGE)
#define SMEM_BYTES (3 * STAGE_HALFS * 2) // 82944 B

template <int EPI>
__global__ void __launch_bounds__(128) rnn_gemm(int t, const int* __restrict__ xids,
                                                const float* __restrict__ b1vec) {
    constexpr int KU = EPI ? (2 * UNITS) : UNITS;
    constexpr int KT = KU / BK;

    const __half* __restrict__ Ag = EPI ? &A1_g[t & 1][0] : &A0_g[(t + 1) & 1][0];
    const __half* __restrict__ Bg = EPI ? B1_g : B0_g;

    extern __shared__ __align__(16) __half sm[];

    const int tid  = threadIdx.x;
    const int lane = tid & 31;
    const int wid  = tid >> 5;
    const int wm   = wid >> 1;      // 2 warp rows (32 rows each)
    const int wn   = wid & 1;       // 2 warp cols (32 cols each)
    const int bm   = blockIdx.y * BM;
    const int bn   = blockIdx.x * BN;

    auto issue = [&](int kb, int s) {
        __half* As = sm + s * STAGE_HALFS;
        __half* Bs = As + AS_STAGE;
        // A tile 64x64 halfs = 512 x 16B chunks, 4 per thread
        #pragma unroll
        for (int j = 0; j < 4; j++) {
            int idx = j * 128 + tid;
            int r = idx >> 3, c = idx & 7;
            const __half* src = Ag + (size_t)(bm + r) * KU + kb * BK + c * 8;
            uint32_t dst = smem_u32(As + r * APITCH + c * 8);
            asm volatile("cp.async.cg.shared.global [%0], [%1], 16;\n" ::"r"(dst), "l"(src));
        }
        // Bhi + Blo tiles, each 64x64 = 512 chunks, 4 per thread each
        #pragma unroll
        for (int j = 0; j < 4; j++) {
            int idx = j * 128 + tid;
            int r = idx >> 3, c = idx & 7;
            const __half* srcH = Bg + (size_t)(kb * BK + r) * UNITS + bn + c * 8;
            const __half* srcL = srcH + (size_t)KU * UNITS;
            uint32_t dstH = smem_u32(Bs + r * APITCH + c * 8);
            uint32_t dstL = dstH + BK * APITCH * 2;
            asm volatile("cp.async.cg.shared.global [%0], [%1], 16;\n" ::"r"(dstH), "l"(srcH));
            asm volatile("cp.async.cg.shared.global [%0], [%1], 16;\n" ::"r"(dstL), "l"(srcL));
        }
        asm volatile("cp.async.commit_group;\n");
    };

    issue(0, 0);
    issue(1, 1);

    float acc[2][4][4];
    #pragma unroll
    for (int i = 0; i < 2; i++)
        #pragma unroll
        for (int j = 0; j < 4; j++)
            #pragma unroll
            for (int q = 0; q < 4; q++) acc[i][j][q] = 0.f;

    const int arow = (lane & 15);
    const int acol = (lane >> 4) << 3;

    for (int kb = 0; kb < KT; kb++) {
        if (kb == KT - 1) asm volatile("cp.async.wait_group 0;\n");
        else              asm volatile("cp.async.wait_group 1;\n");
        __syncthreads();
        if (kb + 2 < KT) issue(kb + 2, (kb + 2) % 3);
        const int s = kb % 3;
        const __half* As = sm + s * STAGE_HALFS;
        const __half* Bs = As + AS_STAGE;

        // fragment double-buffer over 4 k-sub-steps
        uint32_t a[2][2][4], bh[2][2][4], bl[2][2][4];

        auto ldfrag = [&](int ks, int buf) {
            #pragma unroll
            for (int mi = 0; mi < 2; mi++) {
                uint32_t addr = smem_u32(As + (wm * 32 + mi * 16 + arow) * APITCH
                                         + ks * 16 + acol);
                asm volatile("ldmatrix.sync.aligned.m8n8.x4.shared.b16 {%0,%1,%2,%3}, [%4];\n"
                             : "=r"(a[buf][mi][0]), "=r"(a[buf][mi][1]),
                               "=r"(a[buf][mi][2]), "=r"(a[buf][mi][3]) : "r"(addr));
            }
            #pragma unroll
            for (int nh = 0; nh < 2; nh++) {
                uint32_t addrH = smem_u32(Bs + (ks * 16 + arow) * APITCH
                                          + wn * 32 + nh * 16 + acol);
                asm volatile("ldmatrix.sync.aligned.m8n8.x4.trans.shared.b16 {%0,%1,%2,%3}, [%4];\n"
                             : "=r"(bh[buf][nh][0]), "=r"(bh[buf][nh][1]),
                               "=r"(bh[buf][nh][2]), "=r"(bh[buf][nh][3]) : "r"(addrH));
                uint32_t addrL = addrH + BK * APITCH * 2;
                asm volatile("ldmatrix.sync.aligned.m8n8.x4.trans.shared.b16 {%0,%1,%2,%3}, [%4];\n"
                             : "=r"(bl[buf][nh][0]), "=r"(bl[buf][nh][1]),
                               "=r"(bl[buf][nh][2]), "=r"(bl[buf][nh][3]) : "r"(addrL));
            }
        };

        ldfrag(0, 0);
        #pragma unroll
        for (int ks = 0; ks < 4; ks++) {
            const int cur = ks & 1;
            if (ks < 3) ldfrag(ks + 1, cur ^ 1);
            #pragma unroll
            for (int p = 0; p < 2; p++) {
                #pragma unroll
                for (int mi = 0; mi < 2; mi++)
                    #pragma unroll
                    for (int nn = 0; nn < 4; nn++) {
                        uint32_t b0r = p ? bl[cur][nn >> 1][(nn & 1) * 2]
                                         : bh[cur][nn >> 1][(nn & 1) * 2];
                        uint32_t b1r = p ? bl[cur][nn >> 1][(nn & 1) * 2 + 1]
                                         : bh[cur][nn >> 1][(nn & 1) * 2 + 1];
                        float* c = acc[mi][nn];
                        asm volatile(
                            "mma.sync.aligned.m16n8k16.row.col.f32.f16.f16.f32 "
                            "{%0,%1,%2,%3}, {%4,%5,%6,%7}, {%8,%9}, {%0,%1,%2,%3};\n"
                            : "+f"(c[0]), "+f"(c[1]), "+f"(c[2]), "+f"(c[3])
                            : "r"(a[cur][mi][0]), "r"(a[cur][mi][1]),
                              "r"(a[cur][mi][2]), "r"(a[cur][mi][3]),
                              "r"(b0r), "r"(b1r));
                    }
            }
        }
    }

    // ------------- epilogue: tanh + fp16 state writes -------------
    const int r0 = lane >> 2;
    const int cp = lane & 3;
    #pragma unroll
    for (int mi = 0; mi < 2; mi++) {
        #pragma unroll
        for (int rr = 0; rr < 2; rr++) {
            const int b = bm + wm * 32 + mi * 16 + r0 + rr * 8;   // batch row
            const float* addsrc;
            if (EPI == 0) {
                int xi = xids[b * SEQ + t];
                addsrc = EP_g + (size_t)xi * UNITS;
            } else {
                addsrc = b1vec;
            }
            #pragma unroll
            for (int nn = 0; nn < 4; nn++) {
                const int u = bn + wn * 32 + nn * 8 + cp * 2;     // unit col
                float v0 = tanhf(acc[mi][nn][rr * 2 + 0] + addsrc[u]);
                float v1 = tanhf(acc[mi][nn][rr * 2 + 1] + addsrc[u + 1]);
                __half2 h2 = __floats2half2_rn(v0, v1);
                if (EPI == 0) {
                    const int pn = t & 1;
                    *(__half2*)&A0_g[pn][(size_t)b * UNITS + u]       = h2;
                    *(__half2*)&A1_g[pn][(size_t)b * (2 * UNITS) + u] = h2;
                } else {
                    const int pn = (t + 1) & 1;
                    *(__half2*)&A1_g[pn][(size_t)b * (2 * UNITS) + UNITS + u] = h2;
                }
            }
        }
    }
}

// ---------------- output: sigmoid(h1 @ Wout + bout) ----------------
__global__ void out_kernel(const float* __restrict__ Wout, const float* __restrict__ bout,
                           float* __restrict__ out) {
    const int b = blockIdx.x;
    const __half* h1 = &A1_g[0][(size_t)b * (2 * UNITS) + UNITS];   // SEQ even -> phase 0
    float s = 0.f;
    for (int u = threadIdx.x; u < UNITS; u += blockDim.x)
        s += __half2float(h1[u]) * Wout[u];
    #pragma unroll
    for (int o = 16; o; o >>= 1) s += __shfl_xor_sync(0xffffffff, s, o);
    __shared__ float red[4];
    if ((threadIdx.x & 31) == 0) red[threadIdx.x >> 5] = s;
    __syncthreads();
    if (threadIdx.x == 0) {
        float tot = red[0] + red[1] + red[2] + red[3] + bout[0];
        out[b] = 1.f / (1.f + expf(-tot));
    }
}

// ---------------- launcher ----------------
extern "C" void kernel_launch(void* const* d_in, const int* in_sizes, int n_in,
                              void* d_out, int out_size) {
    (void)in_sizes; (void)n_in; (void)out_size;
    const int*   x    = (const int*)d_in[0];
    const float* emb  = (const float*)d_in[1];
    const float* W0x  = (const float*)d_in[2];
    const float* W0h  = (const float*)d_in[3];
    const float* b0   = (const float*)d_in[4];
    const float* W1x  = (const float*)d_in[5];
    const float* W1h  = (const float*)d_in[6];
    const float* b1   = (const float*)d_in[7];
    const float* Wout = (const float*)d_in[8];
    const float* bout = (const float*)d_in[9];
    float* out = (float*)d_out;

    cudaFuncSetAttribute(rnn_gemm<0>, cudaFuncAttributeMaxDynamicSharedMemorySize, SMEM_BYTES);
    cudaFuncSetAttribute(rnn_gemm<1>, cudaFuncAttributeMaxDynamicSharedMemorySize, SMEM_BYTES);

    prep_all<<<1184, 256>>>(W0h, W1x, W1h);
    ep_kernel<<<dim3(UNITS / 128, (VOCAB + 31) / 32), 256>>>(emb, W0x, b0);

    dim3 grid(UNITS / BN, BATCH / BM);     // 16 x 16 = 256 CTAs
    for (int t = 0; t < SEQ; t++) {
        rnn_gemm<0><<<grid, 128, SMEM_BYTES>>>(t, x, b1);
        rnn_gemm<1><<<grid, 128, SMEM_BYTES>>>(t, x, b1);
    }
    out_kernel<<<BATCH, 128>>>(Wout, bout, out);
}

// round 7
// speedup vs baseline: 2.2258x; 1.0365x over previous
#include <cuda_runtime.h>
#include <cuda_fp16.h>
#include <cstdint>
#include <cstddef>

#define VOCAB 10000
#define EMBD  100
#define SEQ   80
#define BATCH 1024
#define UNITS 1024

// ---------------- static device scratch (no allocations allowed) ----------------
__device__ float   EP_g[(size_t)VOCAB * UNITS];             // emb@W0x + b0
__device__ __half  A0_g[2][(size_t)BATCH * UNITS];          // h0 fp16 ping-pong
__device__ __half  A1_g[2][(size_t)BATCH * 2 * UNITS];      // [h0|h1] fp16 ping-pong
__device__ __half  B0_g[(size_t)2 * UNITS * UNITS];         // [W0h_hi ; W0h_lo]  k-major
__device__ __half  B1_g[(size_t)4 * UNITS * UNITS];         // [W1x;W1h]_hi ; _lo k-major

__device__ __forceinline__ uint32_t smem_u32(const void* p) {
    return (uint32_t)__cvta_generic_to_shared(p);
}

// ---------------- fused prep: zero state + split both weight matrices ----------------
__global__ void prep_all(const float* __restrict__ W0h,
                         const float* __restrict__ W1x, const float* __restrict__ W1h) {
    const int nthr = gridDim.x * blockDim.x;
    const int tid  = blockIdx.x * blockDim.x + threadIdx.x;
    {
        const size_t n0 = (size_t)BATCH * UNITS / 8;
        const size_t n1 = (size_t)BATCH * 2 * UNITS / 8;
        uint4 z = make_uint4(0, 0, 0, 0);
        uint4* p0 = (uint4*)&A0_g[1][0];
        uint4* p1 = (uint4*)&A1_g[0][0];
        for (size_t i = tid; i < n0 + n1; i += nthr) {
            if (i < n0) p0[i] = z;
            else        p1[i - n0] = z;
        }
    }
    for (int i = tid; i < 2 * UNITS * UNITS; i += nthr) {
        int r = i / UNITS, c = i % UNITS;
        int lo = r / UNITS;
        int rr = r % UNITS;
        float w = W0h[(size_t)rr * UNITS + c];
        __half hi = __float2half_rn(w);
        B0_g[i] = lo ? __float2half_rn(w - __half2float(hi)) : hi;
    }
    for (int i = tid; i < 4 * UNITS * UNITS; i += nthr) {
        int r = i / UNITS, c = i % UNITS;
        int lo = r / (2 * UNITS);
        int rr = r % (2 * UNITS);
        float w = (rr < UNITS) ? W1x[(size_t)rr * UNITS + c]
                               : W1h[(size_t)(rr - UNITS) * UNITS + c];
        __half hi = __float2half_rn(w);
        B1_g[i] = lo ? __float2half_rn(w - __half2float(hi)) : hi;
    }
}

// ---------------- EP = emb @ W0x + b0  (fp32, M=10000, K=100, N=1024) ----------------
__global__ void __launch_bounds__(256) ep_kernel(const float* __restrict__ emb,
                                                 const float* __restrict__ W0x,
                                                 const float* __restrict__ b0) {
    __shared__ float se[32][EMBD];
    const int rowbase = blockIdx.y * 32;
    const int colbase = blockIdx.x * 128;
    for (int i = threadIdx.x; i < 32 * EMBD; i += 256) {
        int r = i / EMBD, c = i % EMBD;
        int gr = rowbase + r;
        se[r][c] = (gr < VOCAB) ? emb[(size_t)gr * EMBD + c] : 0.f;
    }
    __syncthreads();
    const int ct = threadIdx.x & 31;
    const int rt = threadIdx.x >> 5;
    const int col = colbase + ct * 4;
    float acc[4][4] = {};
    for (int k = 0; k < EMBD; k++) {
        float4 wv = *(const float4*)&W0x[(size_t)k * UNITS + col];
        #pragma unroll
        for (int i = 0; i < 4; i++) {
            float av = se[rt * 4 + i][k];
            acc[i][0] += av * wv.x; acc[i][1] += av * wv.y;
            acc[i][2] += av * wv.z; acc[i][3] += av * wv.w;
        }
    }
    float4 bv = *(const float4*)&b0[col];
    #pragma unroll
    for (int i = 0; i < 4; i++) {
        int gr = rowbase + rt * 4 + i;
        if (gr < VOCAB) {
            float4 o = make_float4(acc[i][0] + bv.x, acc[i][1] + bv.y,
                                   acc[i][2] + bv.z, acc[i][3] + bv.w);
            *(float4*)&EP_g[(size_t)gr * UNITS + col] = o;
        }
    }
}

// ---------------- main recurrent GEMM: 2-group intra-CTA split-K ----------------
// EPI=0: h0_t = tanh(EP[x[b,t]] + h0_{t-1} @ (W0h_hi+W0h_lo))      KU=1024
// EPI=1: h1_t = tanh([h0_t|h1_{t-1}] @ (W_hi+W_lo) + b1)           KU=2048
// CTA: 256 threads = 2 groups x 4 warps (2x2). Tile 64x64, BK=64.
// Group g handles kb % 2 == g with its own 2-stage ring (stages 2g, 2g+1).
#define BM 64
#define BN 64
#define BK 64

#define APITCH 72                        // 64 + 8 halfs pad (144 B rows)
#define AS_STAGE (BM * APITCH)           // 4608 halfs
#define BS_STAGE (2 * BK * APITCH)       // 9216 halfs (hi + lo)
#define STAGE_HALFS (AS_STAGE + BS_STAGE)
#define NSTAGE 4
#define SMEM_BYTES (NSTAGE * STAGE_HALFS * 2)   // 110592 B

template <int EPI>
__global__ void __launch_bounds__(256) rnn_gemm(int t, const int* __restrict__ xids,
                                                const float* __restrict__ b1vec) {
    constexpr int KU = EPI ? (2 * UNITS) : UNITS;
    constexpr int KT = KU / BK;

    const __half* __restrict__ Ag = EPI ? &A1_g[t & 1][0] : &A0_g[(t + 1) & 1][0];
    const __half* __restrict__ Bg = EPI ? B1_g : B0_g;

    extern __shared__ __align__(16) __half sm[];

    const int tid  = threadIdx.x;
    const int lane = tid & 31;
    const int wid  = tid >> 5;          // 0..7
    const int grp  = wid >> 2;          // 0/1
    const int gtid = tid & 127;         // thread id within group
    const int gw   = wid & 3;           // warp within group
    const int wm   = gw >> 1;           // 2 warp rows
    const int wn   = gw & 1;            // 2 warp cols
    const int bm   = blockIdx.y * BM;
    const int bn   = blockIdx.x * BN;

    auto gbar = [&]() {
        asm volatile("bar.sync %0, 128;" :: "r"(grp + 1) : "memory");
    };

    auto issue = [&](int kb, int s) {
        __half* As = sm + s * STAGE_HALFS;
        __half* Bs = As + AS_STAGE;
        #pragma unroll
        for (int j = 0; j < 4; j++) {
            int idx = j * 128 + gtid;
            int r = idx >> 3, c = idx & 7;
            const __half* src = Ag + (size_t)(bm + r) * KU + kb * BK + c * 8;
            uint32_t dst = smem_u32(As + r * APITCH + c * 8);
            asm volatile("cp.async.cg.shared.global [%0], [%1], 16;\n" ::"r"(dst), "l"(src));
        }
        #pragma unroll
        for (int j = 0; j < 4; j++) {
            int idx = j * 128 + gtid;
            int r = idx >> 3, c = idx & 7;
            const __half* srcH = Bg + (size_t)(kb * BK + r) * UNITS + bn + c * 8;
            const __half* srcL = srcH + (size_t)KU * UNITS;
            uint32_t dstH = smem_u32(Bs + r * APITCH + c * 8);
            uint32_t dstL = dstH + BK * APITCH * 2;
            asm volatile("cp.async.cg.shared.global [%0], [%1], 16;\n" ::"r"(dstH), "l"(srcH));
            asm volatile("cp.async.cg.shared.global [%0], [%1], 16;\n" ::"r"(dstL), "l"(srcL));
        }
        asm volatile("cp.async.commit_group;\n");
    };

    auto stage_of = [&](int kb) { return grp * 2 + ((kb >> 1) & 1); };

    issue(grp, stage_of(grp));
    issue(grp + 2, stage_of(grp + 2));

    float acc[2][4][4];
    #pragma unroll
    for (int i = 0; i < 2; i++)
        #pragma unroll
        for (int j = 0; j < 4; j++)
            #pragma unroll
            for (int q = 0; q < 4; q++) acc[i][j][q] = 0.f;

    const int arow = (lane & 15);
    const int acol = (lane >> 4) << 3;

    constexpr int ITERS = KT / 2;
    for (int i = 0; i < ITERS; i++) {
        const int kb = grp + 2 * i;
        if (i == ITERS - 1) asm volatile("cp.async.wait_group 0;\n");
        else                asm volatile("cp.async.wait_group 1;\n");
        gbar();
        const int s = stage_of(kb);
        const __half* As = sm + s * STAGE_HALFS;
        const __half* Bs = As + AS_STAGE;

        uint32_t a[2][2][4], bh[2][2][4], bl[2][2][4];
        auto ldfrag = [&](int ks, int buf) {
            #pragma unroll
            for (int mi = 0; mi < 2; mi++) {
                uint32_t addr = smem_u32(As + (wm * 32 + mi * 16 + arow) * APITCH
                                         + ks * 16 + acol);
                asm volatile("ldmatrix.sync.aligned.m8n8.x4.shared.b16 {%0,%1,%2,%3}, [%4];\n"
                             : "=r"(a[buf][mi][0]), "=r"(a[buf][mi][1]),
                               "=r"(a[buf][mi][2]), "=r"(a[buf][mi][3]) : "r"(addr));
            }
            #pragma unroll
            for (int nh = 0; nh < 2; nh++) {
                uint32_t addrH = smem_u32(Bs + (ks * 16 + arow) * APITCH
                                          + wn * 32 + nh * 16 + acol);
                asm volatile("ldmatrix.sync.aligned.m8n8.x4.trans.shared.b16 {%0,%1,%2,%3}, [%4];\n"
                             : "=r"(bh[buf][nh][0]), "=r"(bh[buf][nh][1]),
                               "=r"(bh[buf][nh][2]), "=r"(bh[buf][nh][3]) : "r"(addrH));
                uint32_t addrL = addrH + BK * APITCH * 2;
                asm volatile("ldmatrix.sync.aligned.m8n8.x4.trans.shared.b16 {%0,%1,%2,%3}, [%4];\n"
                             : "=r"(bl[buf][nh][0]), "=r"(bl[buf][nh][1]),
                               "=r"(bl[buf][nh][2]), "=r"(bl[buf][nh][3]) : "r"(addrL));
            }
        };

        ldfrag(0, 0);
        #pragma unroll
        for (int ks = 0; ks < 4; ks++) {
            const int cur = ks & 1;
            if (ks < 3) ldfrag(ks + 1, cur ^ 1);
            #pragma unroll
            for (int p = 0; p < 2; p++) {
                #pragma unroll
                for (int mi = 0; mi < 2; mi++)
                    #pragma unroll
                    for (int nn = 0; nn < 4; nn++) {
                        uint32_t b0r = p ? bl[cur][nn >> 1][(nn & 1) * 2]
                                         : bh[cur][nn >> 1][(nn & 1) * 2];
                        uint32_t b1r = p ? bl[cur][nn >> 1][(nn & 1) * 2 + 1]
                                         : bh[cur][nn >> 1][(nn & 1) * 2 + 1];
                        float* c = acc[mi][nn];
                        asm volatile(
                            "mma.sync.aligned.m16n8k16.row.col.f32.f16.f16.f32 "
                            "{%0,%1,%2,%3}, {%4,%5,%6,%7}, {%8,%9}, {%0,%1,%2,%3};\n"
                            : "+f"(c[0]), "+f"(c[1]), "+f"(c[2]), "+f"(c[3])
                            : "r"(a[cur][mi][0]), "r"(a[cur][mi][1]),
                              "r"(a[cur][mi][2]), "r"(a[cur][mi][3]),
                              "r"(b0r), "r"(b1r));
                    }
            }
        }
        gbar();                                     // stage free for reuse
        if (kb + 4 < KT) issue(kb + 4, stage_of(kb + 4));
    }

    // ------------- cross-group reduction (group1 -> smem -> group0) -------------
    float* smf = (float*)sm;                        // 128 x 32 fp32 = 16 KB
    __syncthreads();
    if (grp == 1) {
        #pragma unroll
        for (int mi = 0; mi < 2; mi++)
            #pragma unroll
            for (int nn = 0; nn < 4; nn++)
                #pragma unroll
                for (int q = 0; q < 4; q++)
                    smf[(mi * 16 + nn * 4 + q) * 128 + gtid] = acc[mi][nn][q];
    }
    __syncthreads();
    if (grp == 0) {
        #pragma unroll
        for (int mi = 0; mi < 2; mi++)
            #pragma unroll
            for (int nn = 0; nn < 4; nn++)
                #pragma unroll
                for (int q = 0; q < 4; q++)
                    acc[mi][nn][q] += smf[(mi * 16 + nn * 4 + q) * 128 + gtid];

        // ------------- epilogue: tanh + fp16 state writes -------------
        const int r0 = lane >> 2;
        const int cp = lane & 3;
        #pragma unroll
        for (int mi = 0; mi < 2; mi++) {
            #pragma unroll
            for (int rr = 0; rr < 2; rr++) {
                const int b = bm + wm * 32 + mi * 16 + r0 + rr * 8;   // batch row
                const float* addsrc;
                if (EPI == 0) {
                    int xi = xids[b * SEQ + t];
                    addsrc = EP_g + (size_t)xi * UNITS;
                } else {
                    addsrc = b1vec;
                }
                #pragma unroll
                for (int nn = 0; nn < 4; nn++) {
                    const int u = bn + wn * 32 + nn * 8 + cp * 2;     // unit col
                    float v0 = tanhf(acc[mi][nn][rr * 2 + 0] + addsrc[u]);
                    float v1 = tanhf(acc[mi][nn][rr * 2 + 1] + addsrc[u + 1]);
                    __half2 h2 = __floats2half2_rn(v0, v1);
                    if (EPI == 0) {
                        const int pn = t & 1;
                        *(__half2*)&A0_g[pn][(size_t)b * UNITS + u]       = h2;
                        *(__half2*)&A1_g[pn][(size_t)b * (2 * UNITS) + u] = h2;
                    } else {
                        const int pn = (t + 1) & 1;
                        *(__half2*)&A1_g[pn][(size_t)b * (2 * UNITS) + UNITS + u] = h2;
                    }
                }
            }
        }
    }
}

// ---------------- output: sigmoid(h1 @ Wout + bout) ----------------
__global__ void out_kernel(const float* __restrict__ Wout, const float* __restrict__ bout,
                           float* __restrict__ out) {
    const int b = blockIdx.x;
    const __half* h1 = &A1_g[0][(size_t)b * (2 * UNITS) + UNITS];   // SEQ even -> phase 0
    float s = 0.f;
    for (int u = threadIdx.x; u < UNITS; u += blockDim.x)
        s += __half2float(h1[u]) * Wout[u];
    #pragma unroll
    for (int o = 16; o; o >>= 1) s += __shfl_xor_sync(0xffffffff, s, o);
    __shared__ float red[4];
    if ((threadIdx.x & 31) == 0) red[threadIdx.x >> 5] = s;
    __syncthreads();
    if (threadIdx.x == 0) {
        float tot = red[0] + red[1] + red[2] + red[3] + bout[0];
        out[b] = 1.f / (1.f + expf(-tot));
    }
}

// ---------------- launcher ----------------
extern "C" void kernel_launch(void* const* d_in, const int* in_sizes, int n_in,
                              void* d_out, int out_size) {
    (void)in_sizes; (void)n_in; (void)out_size;
    const int*   x    = (const int*)d_in[0];
    const float* emb  = (const float*)d_in[1];
    const float* W0x  = (const float*)d_in[2];
    const float* W0h  = (const float*)d_in[3];
    const float* b0   = (const float*)d_in[4];
    const float* W1x  = (const float*)d_in[5];
    const float* W1h  = (const float*)d_in[6];
    const float* b1   = (const float*)d_in[7];
    const float* Wout = (const float*)d_in[8];
    const float* bout = (const float*)d_in[9];
    float* out = (float*)d_out;

    cudaFuncSetAttribute(rnn_gemm<0>, cudaFuncAttributeMaxDynamicSharedMemorySize, SMEM_BYTES);
    cudaFuncSetAttribute(rnn_gemm<1>, cudaFuncAttributeMaxDynamicSharedMemorySize, SMEM_BYTES);

    prep_all<<<1184, 256>>>(W0h, W1x, W1h);
    ep_kernel<<<dim3(UNITS / 128, (VOCAB + 31) / 32), 256>>>(emb, W0x, b0);

    dim3 grid(UNITS / BN, BATCH / BM);     // 16 x 16 = 256 CTAs
    for (int t = 0; t < SEQ; t++) {
        rnn_gemm<0><<<grid, 256, SMEM_BYTES>>>(t, x, b1);
        rnn_gemm<1><<<grid, 256, SMEM_BYTES>>>(t, x, b1);
    }
    out_kernel<<<BATCH, 128>>>(Wout, bout, out);
}

// round 8
// speedup vs baseline: 3.6157x; 1.6245x over previous
#include <cuda_runtime.h>
#include <cuda_fp16.h>
#include <cstdint>
#include <cstddef>

#define VOCAB 10000
#define EMBD  100
#define SEQ   80
#define BATCH 1024
#define UNITS 1024

// ---------------- static device scratch (no allocations allowed) ----------------
__device__ float   EP_g[(size_t)VOCAB * UNITS];             // emb@W0x + b0
__device__ __half  A0_g[2][(size_t)BATCH * UNITS];          // h0 fp16 ping-pong
__device__ __half  A1_g[2][(size_t)BATCH * 2 * UNITS];      // [h0|h1] fp16 ping-pong
__device__ __half  B0_g[(size_t)UNITS * UNITS];             // W0h fp16, k-major
__device__ __half  B1_g[(size_t)2 * UNITS * UNITS];         // [W1x;W1h] fp16, k-major

__device__ __forceinline__ uint32_t smem_u32(const void* p) {
    return (uint32_t)__cvta_generic_to_shared(p);
}

// ---------------- fused prep: zero state + round both weight matrices ----------------
__global__ void prep_all(const float* __restrict__ W0h,
                         const float* __restrict__ W1x, const float* __restrict__ W1h) {
    const int nthr = gridDim.x * blockDim.x;
    const int tid  = blockIdx.x * blockDim.x + threadIdx.x;
    {
        const size_t n0 = (size_t)BATCH * UNITS / 8;
        const size_t n1 = (size_t)BATCH * 2 * UNITS / 8;
        uint4 z = make_uint4(0, 0, 0, 0);
        uint4* p0 = (uint4*)&A0_g[1][0];
        uint4* p1 = (uint4*)&A1_g[0][0];
        for (size_t i = tid; i < n0 + n1; i += nthr) {
            if (i < n0) p0[i] = z;
            else        p1[i - n0] = z;
        }
    }
    for (int i = tid; i < UNITS * UNITS; i += nthr)
        B0_g[i] = __float2half_rn(W0h[i]);
    for (int i = tid; i < 2 * UNITS * UNITS; i += nthr) {
        int r = i / UNITS, c = i % UNITS;
        float w = (r < UNITS) ? W1x[(size_t)r * UNITS + c]
                              : W1h[(size_t)(r - UNITS) * UNITS + c];
        B1_g[i] = __float2half_rn(w);
    }
}

// ---------------- EP = emb @ W0x + b0  (fp32, M=10000, K=100, N=1024) ----------------
__global__ void __launch_bounds__(256) ep_kernel(const float* __restrict__ emb,
                                                 const float* __restrict__ W0x,
                                                 const float* __restrict__ b0) {
    __shared__ float se[32][EMBD];
    const int rowbase = blockIdx.y * 32;
    const int colbase = blockIdx.x * 128;
    for (int i = threadIdx.x; i < 32 * EMBD; i += 256) {
        int r = i / EMBD, c = i % EMBD;
        int gr = rowbase + r;
        se[r][c] = (gr < VOCAB) ? emb[(size_t)gr * EMBD + c] : 0.f;
    }
    __syncthreads();
    const int ct = threadIdx.x & 31;
    const int rt = threadIdx.x >> 5;
    const int col = colbase + ct * 4;
    float acc[4][4] = {};
    for (int k = 0; k < EMBD; k++) {
        float4 wv = *(const float4*)&W0x[(size_t)k * UNITS + col];
        #pragma unroll
        for (int i = 0; i < 4; i++) {
            float av = se[rt * 4 + i][k];
            acc[i][0] += av * wv.x; acc[i][1] += av * wv.y;
            acc[i][2] += av * wv.z; acc[i][3] += av * wv.w;
        }
    }
    float4 bv = *(const float4*)&b0[col];
    #pragma unroll
    for (int i = 0; i < 4; i++) {
        int gr = rowbase + rt * 4 + i;
        if (gr < VOCAB) {
            float4 o = make_float4(acc[i][0] + bv.x, acc[i][1] + bv.y,
                                   acc[i][2] + bv.z, acc[i][3] + bv.w);
            *(float4*)&EP_g[(size_t)gr * UNITS + col] = o;
        }
    }
}

// ---------------- main recurrent GEMM: 2-group intra-CTA split-K, single fp16 pass ----------------
// EPI=0: h0_t = tanh(EP[x[b,t]] + h0_{t-1} @ W0h)        KU=1024
// EPI=1: h1_t = tanh([h0_t|h1_{t-1}] @ [W1x;W1h] + b1)   KU=2048
// CTA: 256 threads = 2 groups x 4 warps (2x2). Tile 64x64, BK=64.
#define BM 64
#define BN 64
#define BK 64

#define APITCH 72                        // 64 + 8 halfs pad (144 B rows)
#define AS_STAGE (BM * APITCH)           // 4608 halfs
#define BS_STAGE (BK * APITCH)           // 4608 halfs
#define STAGE_HALFS (AS_STAGE + BS_STAGE)
#define NSTAGE 4
#define SMEM_BYTES (NSTAGE * STAGE_HALFS * 2)   // 73728 B

template <int EPI>
__global__ void __launch_bounds__(256) rnn_gemm(int t, const int* __restrict__ xids,
                                                const float* __restrict__ b1vec) {
    constexpr int KU = EPI ? (2 * UNITS) : UNITS;
    constexpr int KT = KU / BK;

    const __half* __restrict__ Ag = EPI ? &A1_g[t & 1][0] : &A0_g[(t + 1) & 1][0];
    const __half* __restrict__ Bg = EPI ? B1_g : B0_g;

    extern __shared__ __align__(16) __half sm[];

    const int tid  = threadIdx.x;
    const int lane = tid & 31;
    const int wid  = tid >> 5;          // 0..7
    const int grp  = wid >> 2;          // 0/1
    const int gtid = tid & 127;
    const int gw   = wid & 3;
    const int wm   = gw >> 1;           // 2 warp rows
    const int wn   = gw & 1;            // 2 warp cols
    const int bm   = blockIdx.y * BM;
    const int bn   = blockIdx.x * BN;

    auto gbar = [&]() {
        asm volatile("bar.sync %0, 128;" :: "r"(grp + 1) : "memory");
    };

    auto issue = [&](int kb, int s) {
        __half* As = sm + s * STAGE_HALFS;
        __half* Bs = As + AS_STAGE;
        #pragma unroll
        for (int j = 0; j < 4; j++) {
            int idx = j * 128 + gtid;
            int r = idx >> 3, c = idx & 7;
            const __half* src = Ag + (size_t)(bm + r) * KU + kb * BK + c * 8;
            uint32_t dst = smem_u32(As + r * APITCH + c * 8);
            asm volatile("cp.async.cg.shared.global [%0], [%1], 16;\n" ::"r"(dst), "l"(src));
        }
        #pragma unroll
        for (int j = 0; j < 4; j++) {
            int idx = j * 128 + gtid;
            int r = idx >> 3, c = idx & 7;
            const __half* src = Bg + (size_t)(kb * BK + r) * UNITS + bn + c * 8;
            uint32_t dst = smem_u32(Bs + r * APITCH + c * 8);
            asm volatile("cp.async.cg.shared.global [%0], [%1], 16;\n" ::"r"(dst), "l"(src));
        }
        asm volatile("cp.async.commit_group;\n");
    };

    auto stage_of = [&](int kb) { return grp * 2 + ((kb >> 1) & 1); };

    issue(grp, stage_of(grp));
    issue(grp + 2, stage_of(grp + 2));

    float acc[2][4][4];
    #pragma unroll
    for (int i = 0; i < 2; i++)
        #pragma unroll
        for (int j = 0; j < 4; j++)
            #pragma unroll
            for (int q = 0; q < 4; q++) acc[i][j][q] = 0.f;

    const int arow = (lane & 15);
    const int acol = (lane >> 4) << 3;

    constexpr int ITERS = KT / 2;
    for (int i = 0; i < ITERS; i++) {
        const int kb = grp + 2 * i;
        if (i == ITERS - 1) asm volatile("cp.async.wait_group 0;\n");
        else                asm volatile("cp.async.wait_group 1;\n");
        gbar();
        const int s = stage_of(kb);
        const __half* As = sm + s * STAGE_HALFS;
        const __half* Bs = As + AS_STAGE;

        uint32_t a[2][2][4], bb[2][2][4];
        auto ldfrag = [&](int ks, int buf) {
            #pragma unroll
            for (int mi = 0; mi < 2; mi++) {
                uint32_t addr = smem_u32(As + (wm * 32 + mi * 16 + arow) * APITCH
                                         + ks * 16 + acol);
                asm volatile("ldmatrix.sync.aligned.m8n8.x4.shared.b16 {%0,%1,%2,%3}, [%4];\n"
                             : "=r"(a[buf][mi][0]), "=r"(a[buf][mi][1]),
                               "=r"(a[buf][mi][2]), "=r"(a[buf][mi][3]) : "r"(addr));
            }
            #pragma unroll
            for (int nh = 0; nh < 2; nh++) {
                uint32_t addr = smem_u32(Bs + (ks * 16 + arow) * APITCH
                                         + wn * 32 + nh * 16 + acol);
                asm volatile("ldmatrix.sync.aligned.m8n8.x4.trans.shared.b16 {%0,%1,%2,%3}, [%4];\n"
                             : "=r"(bb[buf][nh][0]), "=r"(bb[buf][nh][1]),
                               "=r"(bb[buf][nh][2]), "=r"(bb[buf][nh][3]) : "r"(addr));
            }
        };

        ldfrag(0, 0);
        #pragma unroll
        for (int ks = 0; ks < 4; ks++) {
            const int cur = ks & 1;
            if (ks < 3) ldfrag(ks + 1, cur ^ 1);
            #pragma unroll
            for (int mi = 0; mi < 2; mi++)
                #pragma unroll
                for (int nn = 0; nn < 4; nn++) {
                    uint32_t b0r = bb[cur][nn >> 1][(nn & 1) * 2];
                    uint32_t b1r = bb[cur][nn >> 1][(nn & 1) * 2 + 1];
                    float* c = acc[mi][nn];
                    asm volatile(
                        "mma.sync.aligned.m16n8k16.row.col.f32.f16.f16.f32 "
                        "{%0,%1,%2,%3}, {%4,%5,%6,%7}, {%8,%9}, {%0,%1,%2,%3};\n"
                        : "+f"(c[0]), "+f"(c[1]), "+f"(c[2]), "+f"(c[3])
                        : "r"(a[cur][mi][0]), "r"(a[cur][mi][1]),
                          "r"(a[cur][mi][2]), "r"(a[cur][mi][3]),
                          "r"(b0r), "r"(b1r));
                }
        }
        gbar();                                     // stage free for reuse
        if (kb + 4 < KT) issue(kb + 4, stage_of(kb + 4));
    }

    // ------------- cross-group reduction (group1 -> smem -> group0) -------------
    float* smf = (float*)sm;                        // 32 x 128 fp32 = 16 KB
    __syncthreads();
    if (grp == 1) {
        #pragma unroll
        for (int mi = 0; mi < 2; mi++)
            #pragma unroll
            for (int nn = 0; nn < 4; nn++)
                #pragma unroll
                for (int q = 0; q < 4; q++)
                    smf[(mi * 16 + nn * 4 + q) * 128 + gtid] = acc[mi][nn][q];
    }
    __syncthreads();
    if (grp == 0) {
        #pragma unroll
        for (int mi = 0; mi < 2; mi++)
            #pragma unroll
            for (int nn = 0; nn < 4; nn++)
                #pragma unroll
                for (int q = 0; q < 4; q++)
                    acc[mi][nn][q] += smf[(mi * 16 + nn * 4 + q) * 128 + gtid];

        // ------------- epilogue: tanh + fp16 state writes -------------
        const int r0 = lane >> 2;
        const int cp = lane & 3;
        #pragma unroll
        for (int mi = 0; mi < 2; mi++) {
            #pragma unroll
            for (int rr = 0; rr < 2; rr++) {
                const int b = bm + wm * 32 + mi * 16 + r0 + rr * 8;   // batch row
                const float* addsrc;
                if (EPI == 0) {
                    int xi = xids[b * SEQ + t];
                    addsrc = EP_g + (size_t)xi * UNITS;
                } else {
                    addsrc = b1vec;
                }
                #pragma unroll
                for (int nn = 0; nn < 4; nn++) {
                    const int u = bn + wn * 32 + nn * 8 + cp * 2;     // unit col
                    float v0 = tanhf(acc[mi][nn][rr * 2 + 0] + addsrc[u]);
                    float v1 = tanhf(acc[mi][nn][rr * 2 + 1] + addsrc[u + 1]);
                    __half2 h2 = __floats2half2_rn(v0, v1);
                    if (EPI == 0) {
                        const int pn = t & 1;
                        *(__half2*)&A0_g[pn][(size_t)b * UNITS + u]       = h2;
                        *(__half2*)&A1_g[pn][(size_t)b * (2 * UNITS) + u] = h2;
                    } else {
                        const int pn = (t + 1) & 1;
                        *(__half2*)&A1_g[pn][(size_t)b * (2 * UNITS) + UNITS + u] = h2;
                    }
                }
            }
        }
    }
}

// ---------------- output: sigmoid(h1 @ Wout + bout) ----------------
__global__ void out_kernel(const float* __restrict__ Wout, const float* __restrict__ bout,
                           float* __restrict__ out) {
    const int b = blockIdx.x;
    const __half* h1 = &A1_g[0][(size_t)b * (2 * UNITS) + UNITS];   // SEQ even -> phase 0
    float s = 0.f;
    for (int u = threadIdx.x; u < UNITS; u += blockDim.x)
        s += __half2float(h1[u]) * Wout[u];
    #pragma unroll
    for (int o = 16; o; o >>= 1) s += __shfl_xor_sync(0xffffffff, s, o);
    __shared__ float red[4];
    if ((threadIdx.x & 31) == 0) red[threadIdx.x >> 5] = s;
    __syncthreads();
    if (threadIdx.x == 0) {
        float tot = red[0] + red[1] + red[2] + red[3] + bout[0];
        out[b] = 1.f / (1.f + expf(-tot));
    }
}

// ---------------- launcher ----------------
extern "C" void kernel_launch(void* const* d_in, const int* in_sizes, int n_in,
                              void* d_out, int out_size) {
    (void)in_sizes; (void)n_in; (void)out_size;
    const int*   x    = (const int*)d_in[0];
    const float* emb  = (const float*)d_in[1];
    const float* W0x  = (const float*)d_in[2];
    const float* W0h  = (const float*)d_in[3];
    const float* b0   = (const float*)d_in[4];
    const float* W1x  = (const float*)d_in[5];
    const float* W1h  = (const float*)d_in[6];
    const float* b1   = (const float*)d_in[7];
    const float* Wout = (const float*)d_in[8];
    const float* bout = (const float*)d_in[9];
    float* out = (float*)d_out;

    cudaFuncSetAttribute(rnn_gemm<0>, cudaFuncAttributeMaxDynamicSharedMemorySize, SMEM_BYTES);
    cudaFuncSetAttribute(rnn_gemm<1>, cudaFuncAttributeMaxDynamicSharedMemorySize, SMEM_BYTES);

    prep_all<<<1184, 256>>>(W0h, W1x, W1h);
    ep_kernel<<<dim3(UNITS / 128, (VOCAB + 31) / 32), 256>>>(emb, W0x, b0);

    dim3 grid(UNITS / BN, BATCH / BM);     // 16 x 16 = 256 CTAs
    for (int t = 0; t < SEQ; t++) {
        rnn_gemm<0><<<grid, 256, SMEM_BYTES>>>(t, x, b1);
        rnn_gemm<1><<<grid, 256, SMEM_BYTES>>>(t, x, b1);
    }
    out_kernel<<<BATCH, 128>>>(Wout, bout, out);
}